// round 14
// baseline (speedup 1.0000x reference)
#include <cuda_runtime.h>
#include <cuda_bf16.h>

// 3D ROI pooling — single wave, 1024-thread CTAs, x-corner split.
//   img:  (1, 256, 256, 256, 8) fp32, layout ((ix*256+iy)*256+iz)*8 + c
//   rois: (1, 64, 6) int32  [x, y, z, w, h, d]
//   out:  (1, 64, 7, 7, 7, 8) fp32
//
// tid = roi<<11 | px<<8 | py<<5 | pz<<2 | xc<<1 | half   (131072 threads)
// Grid = 128 CTAs x 1024 -> exactly one wave, 32 warps/SM resident.
// Each active thread: 4 independent LDG.128 (y0/y1 x z0/z1 at its x-corner,
// its channel-half), (z,y)-bilinear blend, scale by wx, then shfl_xor(2)
// sums the two x-corner partials. half in lane bit0 -> 32B pair merging.

#define NUM_ROIS 64
#define PS 7
#define CELLS (PS * PS * PS)            // 343
#define DIM 256

__global__ void __launch_bounds__(1024) roi_pool3d_kernel(
    const float* __restrict__ img,
    const int* __restrict__ rois,
    float* __restrict__ out)
{
    int tid = blockIdx.x * 1024 + threadIdx.x;   // 0 .. 131071

    int half = tid & 1;
    int xc   = (tid >> 1) & 1;
    int pz   = (tid >> 2) & 7;
    int py   = (tid >> 5) & 7;
    int px   = (tid >> 8) & 7;
    int roi  = tid >> 11;

    if (px == 7 || py == 7 || pz == 7) return;   // padding lanes (no loads)

    // roi row: 6 ints, 8B aligned -> three int2 loads
    const int2* r2p = (const int2*)(rois + roi * 6);
    int2 rxy = __ldg(r2p + 0);    // x, y
    int2 rzw = __ldg(r2p + 1);    // z, w
    int2 rhd = __ldg(r2p + 2);    // h, d
    int x = rxy.x, y = rxy.y, z = rzw.x;
    int w = rzw.y, h = rhd.x, d = rhd.y;

    // --- axis coords (reference fp32 arithmetic) ---
    float sx = (float)px * ((float)w / (float)PS);
    int ix0 = (int)floorf(sx);
    float fx = sx - (float)ix0;
    int ix1 = min(ix0 + 1, w - 1);
    ix0 = min(ix0, w - 1);

    float sy = (float)py * ((float)h / (float)PS);
    int iy0 = (int)floorf(sy);
    float fy = sy - (float)iy0;
    int iy1 = min(iy0 + 1, h - 1);
    iy0 = min(iy0, h - 1);

    float sz = (float)pz * ((float)d / (float)PS);
    int iz0 = (int)floorf(sz);
    float fz = sz - (float)iz0;
    int iz1 = min(iz0 + 1, d - 1);
    iz0 = min(iz0, d - 1);

    int jx  = x + (xc ? ix1 : ix0);
    int jy0 = y + iy0, jy1 = y + iy1;
    int jz0 = z + iz0, jz1 = z + iz1;

    float wx = xc ? fx : (1.0f - fx);
    float gz = 1.0f - fz, gy = 1.0f - fy;

    // float4 index: ((ix*256+iy)*256+iz)*2 + half
    const float4* __restrict__ base = (const float4*)img;
    int row0 = (jx * DIM + jy0) * DIM;
    int row1 = (jx * DIM + jy1) * DIM;

    size_t b00 = (size_t)(row0 + jz0) * 2 + half;
    size_t b01 = (size_t)(row0 + jz1) * 2 + half;
    size_t b10 = (size_t)(row1 + jz0) * 2 + half;
    size_t b11 = (size_t)(row1 + jz1) * 2 + half;

    // 4 independent LDG.128
    float4 v00 = base[b00];
    float4 v01 = base[b01];
    float4 v10 = base[b10];
    float4 v11 = base[b11];

    // (z, y) bilinear, scaled by this x-corner's weight
    float4 p;
    p.x = ((v00.x * gz + v01.x * fz) * gy + (v10.x * gz + v11.x * fz) * fy) * wx;
    p.y = ((v00.y * gz + v01.y * fz) * gy + (v10.y * gz + v11.y * fz) * fy) * wx;
    p.z = ((v00.z * gz + v01.z * fz) * gy + (v10.z * gz + v11.z * fz) * fy) * wx;
    p.w = ((v00.w * gz + v01.w * fz) * gy + (v10.w * gz + v11.w * fz) * fy) * wx;

    // sum x-corner pair (lane bit 1). Partner lane shares the pad predicate,
    // so it is always present in the active mask.
    unsigned m = __activemask();
    p.x += __shfl_xor_sync(m, p.x, 2);
    p.y += __shfl_xor_sync(m, p.y, 2);
    p.z += __shfl_xor_sync(m, p.z, 2);
    p.w += __shfl_xor_sync(m, p.w, 2);

    if (xc == 0) {
        int cell = (px * PS + py) * PS + pz;
        ((float4*)out)[(size_t)(roi * CELLS + cell) * 2 + half] = p;
    }
}

extern "C" void kernel_launch(void* const* d_in, const int* in_sizes, int n_in,
                              void* d_out, int out_size)
{
    const float* img  = (const float*)d_in[0];
    const int*   rois = (const int*)d_in[1];
    float*       out  = (float*)d_out;

    // 64 rois * 2048 padded slots = 131072 threads = 128 CTAs x 1024 (one wave)
    roi_pool3d_kernel<<<128, 1024>>>(img, rois, out);
}

// round 15
// speedup vs baseline: 1.2593x; 1.2593x over previous
#include <cuda_runtime.h>
#include <cuda_bf16.h>

// 3D ROI pooling — all-148-SM single wave + shortened front chain.
//   img:  (1, 256, 256, 256, 8) fp32, layout ((ix*256+iy)*256+iz)*8 + c
//   rois: (1, 64, 6) int32  [x, y, z, w, h, d]
//   out:  (1, 64, 7, 7, 7, 8) fp32
//
// Padded index space: tid = roi<<10 | px<<7 | py<<4 | pz<<1 | half (65536).
// Grid = 148 CTAs x 448 threads (66304 threads, guard tid<65536) -> one CTA
// per SM, all 148 SMs share the sector-service load. 8 independent LDG.128
// per active thread; divides replaced by *(1/7) to shorten the lead chain.

#define NUM_ROIS 64
#define PS 7
#define CELLS (PS * PS * PS)            // 343
#define DIM 256
#define INV_PS (1.0f / 7.0f)

__global__ void __launch_bounds__(448) roi_pool3d_kernel(
    const float* __restrict__ img,
    const int* __restrict__ rois,
    float* __restrict__ out)
{
    int tid = blockIdx.x * 448 + threadIdx.x;
    if (tid >= 65536) return;

    int half = tid & 1;
    int pz   = (tid >> 1) & 7;
    int py   = (tid >> 4) & 7;
    int px   = (tid >> 7) & 7;
    int roi  = tid >> 10;

    if (px == 7 || py == 7 || pz == 7) return;   // padding lanes

    // roi row: 6 ints, 8B aligned -> three int2 loads
    const int2* r2p = (const int2*)(rois + roi * 6);
    int2 rxy = __ldg(r2p + 0);    // x, y
    int2 rzw = __ldg(r2p + 1);    // z, w
    int2 rhd = __ldg(r2p + 2);    // h, d
    int x = rxy.x, y = rxy.y, z = rzw.x;
    int w = rzw.y, h = rhd.x, d = rhd.y;

    // --- axis coords; mul-by-inverse instead of divide (tolerance 1e-3) ---
    float sx = (float)px * ((float)w * INV_PS);
    int ix0 = (int)floorf(sx);
    float fx = sx - (float)ix0;
    int ix1 = min(ix0 + 1, w - 1);
    ix0 = min(ix0, w - 1);

    float sy = (float)py * ((float)h * INV_PS);
    int iy0 = (int)floorf(sy);
    float fy = sy - (float)iy0;
    int iy1 = min(iy0 + 1, h - 1);
    iy0 = min(iy0, h - 1);

    float sz = (float)pz * ((float)d * INV_PS);
    int iz0 = (int)floorf(sz);
    float fz = sz - (float)iz0;
    int iz1 = min(iz0 + 1, d - 1);
    iz0 = min(iz0, d - 1);

    int jx0 = x + ix0, jx1 = x + ix1;
    int jy0 = y + iy0, jy1 = y + iy1;
    int jz0 = z + iz0, jz1 = z + iz1;

    // float4 index: ((ix*256+iy)*256+iz)*2 + half
    const float4* __restrict__ base = (const float4*)img;
    int row00 = (jx0 * DIM + jy0) * DIM;
    int row01 = (jx0 * DIM + jy1) * DIM;
    int row10 = (jx1 * DIM + jy0) * DIM;
    int row11 = (jx1 * DIM + jy1) * DIM;

    size_t b000 = (size_t)(row00 + jz0) * 2 + half;
    size_t b001 = (size_t)(row00 + jz1) * 2 + half;
    size_t b010 = (size_t)(row01 + jz0) * 2 + half;
    size_t b011 = (size_t)(row01 + jz1) * 2 + half;
    size_t b100 = (size_t)(row10 + jz0) * 2 + half;
    size_t b101 = (size_t)(row10 + jz1) * 2 + half;
    size_t b110 = (size_t)(row11 + jz0) * 2 + half;
    size_t b111 = (size_t)(row11 + jz1) * 2 + half;

    // 8 independent LDG.128 (MLP = 8)
    float4 v000 = base[b000];
    float4 v001 = base[b001];
    float4 v010 = base[b010];
    float4 v011 = base[b011];
    float4 v100 = base[b100];
    float4 v101 = base[b101];
    float4 v110 = base[b110];
    float4 v111 = base[b111];

    float gz = 1.0f - fz, gy = 1.0f - fy, gx = 1.0f - fx;

    float4 o;
    {
        float c00, c01, c10, c11, c0, c1;
        c00 = v000.x * gz + v001.x * fz;
        c01 = v010.x * gz + v011.x * fz;
        c10 = v100.x * gz + v101.x * fz;
        c11 = v110.x * gz + v111.x * fz;
        c0 = c00 * gy + c01 * fy;
        c1 = c10 * gy + c11 * fy;
        o.x = c0 * gx + c1 * fx;

        c00 = v000.y * gz + v001.y * fz;
        c01 = v010.y * gz + v011.y * fz;
        c10 = v100.y * gz + v101.y * fz;
        c11 = v110.y * gz + v111.y * fz;
        c0 = c00 * gy + c01 * fy;
        c1 = c10 * gy + c11 * fy;
        o.y = c0 * gx + c1 * fx;

        c00 = v000.z * gz + v001.z * fz;
        c01 = v010.z * gz + v011.z * fz;
        c10 = v100.z * gz + v101.z * fz;
        c11 = v110.z * gz + v111.z * fz;
        c0 = c00 * gy + c01 * fy;
        c1 = c10 * gy + c11 * fy;
        o.z = c0 * gx + c1 * fx;

        c00 = v000.w * gz + v001.w * fz;
        c01 = v010.w * gz + v011.w * fz;
        c10 = v100.w * gz + v101.w * fz;
        c11 = v110.w * gz + v111.w * fz;
        c0 = c00 * gy + c01 * fy;
        c1 = c10 * gy + c11 * fy;
        o.w = c0 * gx + c1 * fx;
    }

    // output vec index = (roi*343 + ((px*7+py)*7+pz))*2 + half
    int cell = (px * PS + py) * PS + pz;
    ((float4*)out)[(size_t)(roi * CELLS + cell) * 2 + half] = o;
}

extern "C" void kernel_launch(void* const* d_in, const int* in_sizes, int n_in,
                              void* d_out, int out_size)
{
    const float* img  = (const float*)d_in[0];
    const int*   rois = (const int*)d_in[1];
    float*       out  = (float*)d_out;

    // 148 CTAs x 448 threads = 66304 >= 65536 padded slots; one CTA per SM.
    roi_pool3d_kernel<<<148, 448>>>(img, rois, out);
}